// round 13
// baseline (speedup 1.0000x reference)
#include <cuda_runtime.h>
#include <float.h>

#define TT   3
#define HH   192
#define WW   192
#define CC   64
#define HWSZ (HH*WW)
#define NHC  24
#define NWC  24
#define Q1   (TT*NHC*NWC)   // 1728
#define NHF  48
#define NWF  48
#define QF   (TT*NHF*NWF)   // 6912
#define KK   7
#define SS   192            // candidates per query

// scratch (static __device__ arrays — allowed; no runtime allocation)
__device__ float g_v0t[TT*HWSZ*CC];
__device__ float g_v1t[TT*HWSZ*CC];
__device__ float g_sd[Q1*SS];
__device__ int   g_inds[Q1*KK*3];

__device__ __forceinline__ int refl(int i, int L) {
    i = i < 0 ? -i : i;
    return (i >= L) ? (2*(L-1) - i) : i;
}

// ---------------------------------------------------------------------------
// Transpose (T,C,H,W) -> (T,H,W,C), channels-last, for both videos.
// ---------------------------------------------------------------------------
__global__ void __launch_bounds__(256) transpose_kernel(const float* __restrict__ v0,
                                                        const float* __restrict__ v1) {
    const float* src = (blockIdx.z == 0) ? v0 : v1;
    float* dst       = (blockIdx.z == 0) ? g_v0t : g_v1t;
    const int t    = blockIdx.y;
    const int pix0 = blockIdx.x * 32;

    __shared__ float tile[CC][33];
    const int tx  = threadIdx.x & 31;
    const int grp = threadIdx.x >> 5;   // 0..7

    #pragma unroll
    for (int cc = 0; cc < CC; cc += 8) {
        int c = cc + grp;
        tile[c][tx] = src[((size_t)(t*CC + c))*HWSZ + pix0 + tx];
    }
    __syncthreads();
    #pragma unroll
    for (int i = 0; i < 8; ++i) {
        int idx = i*256 + threadIdx.x;        // 0..2047
        int pix = idx >> 6;                   // 0..31
        int ch  = idx & 63;
        dst[((size_t)t*HWSZ + pix0 + pix)*CC + ch] = tile[ch][pix];
    }
}

// ---------------------------------------------------------------------------
// Stage 1a v9 (unchanged from R12): 6-query blocks, quad packing, SW pipeline.
// Per candidate, per offset (dri,ox): p = sequential fma chain over c=0..63,
// then acc += p in (dri major, ox ascending) order. DO NOT REORDER the
// arithmetic — it reproduces the reference's fp tie resolution bit-for-bit.
// ---------------------------------------------------------------------------
#define NQB     6                     // queries per block
#define WCOLS   (8*NQB + 6)           // 54 col slots
#define CSTR2   68                    // col-slot stride (floats)
#define ROWSTR2 (WCOLS*CSTR2 + 12)    // 3684 floats; mod 32 == 4 (conflict-free)
#define SV_BYTES (14*ROWSTR2*4)       // 206304 bytes dynamic smem

#define LOAD_WA(wb, ab, c4)                                                   \
    do {                                                                      \
        _Pragma("unroll")                                                     \
        for (int j = 0; j < 10; ++j)                                          \
            wb[j] = *reinterpret_cast<const float4*>(vrow + j*CSTR2 + (c4)*4);\
        _Pragma("unroll")                                                     \
        for (int ox = 0; ox < 7; ++ox)                                        \
            ab[ox] = *reinterpret_cast<const float4*>(qrow + xq[ox] + (c4)*4);\
    } while (0)

#define COMPUTE_WA(wb, ab)                                                    \
    do {                                                                      \
        _Pragma("unroll")                                                     \
        for (int d = 0; d < 4; ++d) {                                         \
            _Pragma("unroll")                                                 \
            for (int ox = 0; ox < 7; ++ox) {                                  \
                float4 b = wb[d + ox];                                        \
                p[d][ox] = fmaf(ab[ox].x, b.x, p[d][ox]);                     \
                p[d][ox] = fmaf(ab[ox].y, b.y, p[d][ox]);                     \
                p[d][ox] = fmaf(ab[ox].z, b.z, p[d][ox]);                     \
                p[d][ox] = fmaf(ab[ox].w, b.w, p[d][ox]);                     \
            }                                                                 \
        }                                                                     \
    } while (0)

__global__ void __launch_bounds__(288, 1) stage1a_kernel() {
    extern __shared__ float sv[];

    const int qj0 = blockIdx.x * NQB;
    const int qi  = blockIdx.y;
    const int t   = blockIdx.z;
    const int qh  = qi * 8;
    const int qw0 = qj0 * 8;

    const int tid  = threadIdx.x;
    const int slot = tid >> 4;        // 0..17
    const int u    = slot % NQB;      // query within block
    const int qt   = slot / NQB;      // 0..2
    const int sub  = tid & 15;
    const int dyi  = sub >> 1;        // 0..7
    const int quad = sub & 1;         // 0..1 -> dxi base 4*quad

    // cooperative load: candidate window (once)
    const float* v1base = g_v1t + (size_t)t*HWSZ*CC;
    for (int i = tid; i < 14*WCOLS*16; i += 288) {
        int r   = i / (WCOLS*16);
        int rem = i % (WCOLS*16);
        int s   = rem >> 4;
        int c4  = rem & 15;
        int y = refl(qh - 7 + r, HH);
        int x = refl(qw0 - 7 + s, WW);
        float4 v = reinterpret_cast<const float4*>(v1base + ((size_t)y*WW + x)*CC)[c4];
        *reinterpret_cast<float4*>(sv + r*ROWSTR2 + s*CSTR2 + c4*4) = v;
    }
    __syncthreads();

    const int q  = qt*(NHC*NWC) + qi*NWC + (qj0 + u);
    const int qw = qw0 + u*8;

    // query patch col element-offsets (uniform within slot)
    int xq[7];
    #pragma unroll
    for (int ox = 0; ox < 7; ++ox) xq[ox] = refl(qw + ox - 3, WW) * CC;
    const float* v0base = g_v0t + (size_t)qt*HWSZ*CC;

    float acc[4] = {0.f, 0.f, 0.f, 0.f};
    const float* svw = sv + (8*u + 4*quad)*CSTR2;

    for (int dri = 0; dri < 7; ++dri) {
        const int yq = refl(qh + dri - 3, HH);
        const float* qrow = v0base + (size_t)yq*WW*CC;
        const float* vrow = svw + (dyi + dri)*ROWSTR2;

        float p[4][7];
        #pragma unroll
        for (int d = 0; d < 4; ++d)
            #pragma unroll
            for (int ox = 0; ox < 7; ++ox) p[d][ox] = 0.f;

        // software pipeline: prefetch one c4-iter ahead into alternating bufs
        float4 w0[10], a0[7], w1[10], a1[7];
        LOAD_WA(w0, a0, 0);
        #pragma unroll
        for (int c4 = 0; c4 < 16; c4 += 2) {
            LOAD_WA(w1, a1, c4 + 1);     // prefetch c4+1
            COMPUTE_WA(w0, a0);          // compute c4
            if (c4 + 2 < 16)
                LOAD_WA(w0, a0, c4 + 2); // prefetch c4+2
            COMPUTE_WA(w1, a1);          // compute c4+1
        }
        #pragma unroll
        for (int d = 0; d < 4; ++d)
            #pragma unroll
            for (int ox = 0; ox < 7; ++ox) acc[d] += p[d][ox];
    }

    float4 res = make_float4(acc[0], acc[1], acc[2], acc[3]);
    *reinterpret_cast<float4*>(&g_sd[q*SS + t*64 + dyi*8 + 4*quad]) = res;
}

// ---------------------------------------------------------------------------
// Stage 1b: warp-per-query top-7 via shuffles (no block syncs).
// Stable: ties -> lowest candidate index (lax.top_k semantics).
// ---------------------------------------------------------------------------
__global__ void __launch_bounds__(256) stage1b_kernel() {
    const int lane = threadIdx.x & 31;
    const int q = blockIdx.x*8 + (threadIdx.x >> 5);
    const int rr = q % (NHC*NWC);
    const int qh = (rr / NWC) * 8;
    const int qw = (rr % NWC) * 8;

    float v[6];
    #pragma unroll
    for (int j = 0; j < 6; ++j) v[j] = g_sd[q*SS + j*32 + lane];

    #pragma unroll 1
    for (int k = 0; k < KK; ++k) {
        float bv = v[0]; int bi = lane;
        #pragma unroll
        for (int j = 1; j < 6; ++j) {
            if (v[j] > bv) { bv = v[j]; bi = j*32 + lane; }
        }
        #pragma unroll
        for (int s = 16; s > 0; s >>= 1) {
            float ov = __shfl_xor_sync(0xffffffffu, bv, s);
            int   oi = __shfl_xor_sync(0xffffffffu, bi, s);
            if (ov > bv || (ov == bv && oi < bi)) { bv = ov; bi = oi; }
        }
        if (lane == 0) {
            int base = (q*KK + k)*3;
            g_inds[base + 0] = bi >> 6;                   // ct
            g_inds[base + 1] = qh + ((bi >> 3) & 7) - 4;  // ch (raw)
            g_inds[base + 2] = qw + (bi & 7) - 4;         // cw (raw)
        }
        if ((bi & 31) == lane) {
            int jj = bi >> 5;
            #pragma unroll
            for (int j = 0; j < 6; ++j) if (j == jj) v[j] = -FLT_MAX;
        }
    }
}

// ---------------------------------------------------------------------------
// Stage 2+3 fused v6: 14 warps per block — TWO warps per candidate, split by
// offset parity (o = 4i + 2par + h), warp-local reduce, smem partial combine.
// dists_f is tolerance-checked, so this summation partition is free.
// block = 448 threads; warp w: k = w>>1, h = w&1; lanes: par = lane>>4,
// c16 = lane&15 (channel quad).
// ---------------------------------------------------------------------------
__global__ void __launch_bounds__(448) stage3_kernel(float* __restrict__ out) {
    const int q  = blockIdx.x;
    const int ft = q / (NHF*NWF);
    const int rr = q % (NHF*NWF);
    const int fi = rr / NWF, fj = rr % NWF;
    const int fh = fi*4, fw = fj*4;

    __shared__ float sp[49*CC];
    __shared__ int   scand[KK*3];
    __shared__ int   soff[KK*49];
    __shared__ float spart[KK*2];

    const int tid = threadIdx.x;
    // query patch, vectorized
    for (int i = tid; i < 49*16; i += 448) {
        int o = i >> 4, c4 = i & 15;
        int y = refl(fh + (o/7) - 3, HH);
        int x = refl(fw + (o%7) - 3, WW);
        reinterpret_cast<float4*>(sp)[i] =
            reinterpret_cast<const float4*>(g_v0t + ((size_t)ft*HWSZ + (size_t)y*WW + x)*CC)[c4];
    }
    if (tid < KK) {
        int it, ih, iw;
        if (tid == 0) { it = ft; ih = fh; iw = fw; }
        else {
            int ci = min(fi >> 1, NHC - 1);
            int cj = min(fj >> 1, NWC - 1);
            int qlin = ft*NHC*NWC + ci*NWC + cj;
            int b = (qlin*KK + tid)*3;
            it = g_inds[b + 0];
            ih = refl(g_inds[b + 1] + (fh - ci*8), HH);
            iw = refl(g_inds[b + 2] + (fw - cj*8), WW);
        }
        scand[tid*3 + 0] = it;
        scand[tid*3 + 1] = ih;
        scand[tid*3 + 2] = iw;
        // inds_f (as float), laid out after dists_f
        size_t ob = (size_t)QF*KK + ((size_t)q*KK + tid)*3;
        out[ob + 0] = (float)it;
        out[ob + 1] = (float)ih;
        out[ob + 2] = (float)iw;
    }
    __syncthreads();

    // cooperative offset table: soff[k*49+o] = (y1*W + x1)*CC (element offset)
    for (int i = tid; i < KK*49; i += 448) {
        int k = i / 49, o = i % 49;
        int y1 = refl(scand[k*3 + 1] + o/7 - 3, HH);
        int x1 = refl(scand[k*3 + 2] + o%7 - 3, WW);
        soff[i] = (y1*WW + x1)*CC;
    }
    __syncthreads();

    const int warp = tid >> 5;        // 0..13
    const int k    = warp >> 1;       // candidate
    const int h    = warp & 1;        // offset-parity group
    const int lane = tid & 31;
    const int par  = lane >> 4;       // sub-parity within warp
    const int c16  = lane & 15;       // channel quad
    const int it = scand[k*3 + 0];
    const float* v1b = g_v1t + (size_t)it*HWSZ*CC + 4*c16;
    const int* mysoff = soff + k*49;
    const float* spl = sp + 4*c16;

    float4 acc = make_float4(0.f, 0.f, 0.f, 0.f);
    #pragma unroll
    for (int i = 0; i < 13; ++i) {
        int o  = 4*i + 2*par + h;       // each o in [0,49) hit exactly once
        int oc = (o < 49) ? o : 0;      // clamp (masked below)
        float m = (o < 49) ? 1.f : 0.f;
        float4 wv = *reinterpret_cast<const float4*>(v1b + mysoff[oc]);
        float4 pv = *reinterpret_cast<const float4*>(spl + oc*CC);
        acc.x = fmaf(pv.x*m, wv.x, acc.x);
        acc.y = fmaf(pv.y*m, wv.y, acc.y);
        acc.z = fmaf(pv.z*m, wv.z, acc.z);
        acc.w = fmaf(pv.w*m, wv.w, acc.w);
    }
    float v = (acc.x + acc.y) + (acc.z + acc.w);
    #pragma unroll
    for (int s = 16; s > 0; s >>= 1)
        v += __shfl_down_sync(0xffffffffu, v, s);
    if (lane == 0)
        spart[k*2 + h] = v;
    __syncthreads();

    if (tid < KK)
        out[(size_t)q*KK + tid] = spart[tid*2] + spart[tid*2 + 1];
}

// ---------------------------------------------------------------------------
extern "C" void kernel_launch(void* const* d_in, const int* in_sizes, int n_in,
                              void* d_out, int out_size) {
    const float* vid0 = (const float*)d_in[0];
    const float* vid1 = (const float*)d_in[1];
    // d_in[2] = flows, unused by the reference

    cudaFuncSetAttribute(stage1a_kernel,
                         cudaFuncAttributeMaxDynamicSharedMemorySize, SV_BYTES);

    dim3 tgrid(HWSZ/32, TT, 2);
    transpose_kernel<<<tgrid, 256>>>(vid0, vid1);
    stage1a_kernel<<<dim3(NWC/NQB, NHC, TT), 288, SV_BYTES>>>();
    stage1b_kernel<<<Q1/8, 256>>>();
    stage3_kernel<<<QF, 448>>>((float*)d_out);
}

// round 14
// speedup vs baseline: 1.0310x; 1.0310x over previous
#include <cuda_runtime.h>
#include <float.h>

#define TT   3
#define HH   192
#define WW   192
#define CC   64
#define HWSZ (HH*WW)
#define NHC  24
#define NWC  24
#define Q1   (TT*NHC*NWC)   // 1728
#define NHF  48
#define NWF  48
#define QF   (TT*NHF*NWF)   // 6912
#define KK   7
#define SS   192            // candidates per query

// scratch (static __device__ arrays — allowed; no runtime allocation)
__device__ float g_v0t[TT*HWSZ*CC];
__device__ float g_v1t[TT*HWSZ*CC];
__device__ float g_sd[Q1*SS];
__device__ int   g_inds[Q1*KK*3];

__device__ __forceinline__ int refl(int i, int L) {
    i = i < 0 ? -i : i;
    return (i >= L) ? (2*(L-1) - i) : i;
}

// rotate the ncu fixed capture slot onto stage1a (diagnostic)
__global__ void dummy_kernel() {}

// ---------------------------------------------------------------------------
// Transpose (T,C,H,W) -> (T,H,W,C), channels-last, for both videos.
// ---------------------------------------------------------------------------
__global__ void __launch_bounds__(256) transpose_kernel(const float* __restrict__ v0,
                                                        const float* __restrict__ v1) {
    const float* src = (blockIdx.z == 0) ? v0 : v1;
    float* dst       = (blockIdx.z == 0) ? g_v0t : g_v1t;
    const int t    = blockIdx.y;
    const int pix0 = blockIdx.x * 32;

    __shared__ float tile[CC][33];
    const int tx  = threadIdx.x & 31;
    const int grp = threadIdx.x >> 5;   // 0..7

    #pragma unroll
    for (int cc = 0; cc < CC; cc += 8) {
        int c = cc + grp;
        tile[c][tx] = src[((size_t)(t*CC + c))*HWSZ + pix0 + tx];
    }
    __syncthreads();
    #pragma unroll
    for (int i = 0; i < 8; ++i) {
        int idx = i*256 + threadIdx.x;        // 0..2047
        int pix = idx >> 6;                   // 0..31
        int ch  = idx & 63;
        dst[((size_t)t*HWSZ + pix0 + pix)*CC + ch] = tile[ch][pix];
    }
}

// ---------------------------------------------------------------------------
// Stage 1a v10: v9 structure with a ROLLED steady-state software pipeline
// (hot loop ~9 KB, fits L1.5 I$) + peeled epilogue.
// grid (4, 24, 3): block = (6 adjacent queries, row qi, t). 288 thr.
// query-slot = tid>>4; u = slot%6, qt = slot/6; sub = tid&15; dyi = sub>>1;
// quad = sub&1 -> candidates dxi = 4*quad..4*quad+3.
// Per candidate, per offset (dri,ox): p = sequential fma chain over c=0..63,
// then acc += p in (dri major, ox ascending) order. DO NOT REORDER the
// arithmetic — it reproduces the reference's fp tie resolution bit-for-bit.
// ---------------------------------------------------------------------------
#define NQB     6                     // queries per block
#define WCOLS   (8*NQB + 6)           // 54 col slots
#define CSTR2   68                    // col-slot stride (floats)
#define ROWSTR2 (WCOLS*CSTR2 + 12)    // 3684 floats; mod 32 == 4 (conflict-free)
#define SV_BYTES (14*ROWSTR2*4)       // 206304 bytes dynamic smem

#define LOAD_WA(wb, ab, c4)                                                   \
    do {                                                                      \
        _Pragma("unroll")                                                     \
        for (int j = 0; j < 10; ++j)                                          \
            wb[j] = *reinterpret_cast<const float4*>(vrow + j*CSTR2 + (c4)*4);\
        _Pragma("unroll")                                                     \
        for (int ox = 0; ox < 7; ++ox)                                        \
            ab[ox] = *reinterpret_cast<const float4*>(qrow + xq[ox] + (c4)*4);\
    } while (0)

#define COMPUTE_WA(wb, ab)                                                    \
    do {                                                                      \
        _Pragma("unroll")                                                     \
        for (int d = 0; d < 4; ++d) {                                         \
            _Pragma("unroll")                                                 \
            for (int ox = 0; ox < 7; ++ox) {                                  \
                float4 b = wb[d + ox];                                        \
                p[d][ox] = fmaf(ab[ox].x, b.x, p[d][ox]);                     \
                p[d][ox] = fmaf(ab[ox].y, b.y, p[d][ox]);                     \
                p[d][ox] = fmaf(ab[ox].z, b.z, p[d][ox]);                     \
                p[d][ox] = fmaf(ab[ox].w, b.w, p[d][ox]);                     \
            }                                                                 \
        }                                                                     \
    } while (0)

__global__ void __launch_bounds__(288, 1) stage1a_kernel() {
    extern __shared__ float sv[];

    const int qj0 = blockIdx.x * NQB;
    const int qi  = blockIdx.y;
    const int t   = blockIdx.z;
    const int qh  = qi * 8;
    const int qw0 = qj0 * 8;

    const int tid  = threadIdx.x;
    const int slot = tid >> 4;        // 0..17
    const int u    = slot % NQB;      // query within block
    const int qt   = slot / NQB;      // 0..2
    const int sub  = tid & 15;
    const int dyi  = sub >> 1;        // 0..7
    const int quad = sub & 1;         // 0..1 -> dxi base 4*quad

    // cooperative load: candidate window (once)
    const float* v1base = g_v1t + (size_t)t*HWSZ*CC;
    for (int i = tid; i < 14*WCOLS*16; i += 288) {
        int r   = i / (WCOLS*16);
        int rem = i % (WCOLS*16);
        int s   = rem >> 4;
        int c4  = rem & 15;
        int y = refl(qh - 7 + r, HH);
        int x = refl(qw0 - 7 + s, WW);
        float4 v = reinterpret_cast<const float4*>(v1base + ((size_t)y*WW + x)*CC)[c4];
        *reinterpret_cast<float4*>(sv + r*ROWSTR2 + s*CSTR2 + c4*4) = v;
    }
    __syncthreads();

    const int q  = qt*(NHC*NWC) + qi*NWC + (qj0 + u);
    const int qw = qw0 + u*8;

    // query patch col element-offsets (uniform within slot)
    int xq[7];
    #pragma unroll
    for (int ox = 0; ox < 7; ++ox) xq[ox] = refl(qw + ox - 3, WW) * CC;
    const float* v0base = g_v0t + (size_t)qt*HWSZ*CC;

    float acc[4] = {0.f, 0.f, 0.f, 0.f};
    const float* svw = sv + (8*u + 4*quad)*CSTR2;

    #pragma unroll 1
    for (int dri = 0; dri < 7; ++dri) {
        const int yq = refl(qh + dri - 3, HH);
        const float* qrow = v0base + (size_t)yq*WW*CC;
        const float* vrow = svw + (dyi + dri)*ROWSTR2;

        float p[4][7];
        #pragma unroll
        for (int d = 0; d < 4; ++d)
            #pragma unroll
            for (int ox = 0; ox < 7; ++ox) p[d][ox] = 0.f;

        // software pipeline, ROLLED steady state (small I$ footprint)
        float4 w0[10], a0[7], w1[10], a1[7];
        LOAD_WA(w0, a0, 0);
        #pragma unroll 1
        for (int c4 = 0; c4 < 12; c4 += 2) {
            LOAD_WA(w1, a1, c4 + 1);     // prefetch odd
            COMPUTE_WA(w0, a0);          // compute even
            LOAD_WA(w0, a0, c4 + 2);     // prefetch next even
            COMPUTE_WA(w1, a1);          // compute odd
        }
        // peeled epilogue: c4 = 12..15 (no out-of-range prefetch)
        LOAD_WA(w1, a1, 13);
        COMPUTE_WA(w0, a0);              // 12
        LOAD_WA(w0, a0, 14);
        COMPUTE_WA(w1, a1);              // 13
        LOAD_WA(w1, a1, 15);
        COMPUTE_WA(w0, a0);              // 14
        COMPUTE_WA(w1, a1);              // 15

        #pragma unroll
        for (int d = 0; d < 4; ++d)
            #pragma unroll
            for (int ox = 0; ox < 7; ++ox) acc[d] += p[d][ox];
    }

    float4 res = make_float4(acc[0], acc[1], acc[2], acc[3]);
    *reinterpret_cast<float4*>(&g_sd[q*SS + t*64 + dyi*8 + 4*quad]) = res;
}

// ---------------------------------------------------------------------------
// Stage 1b: warp-per-query top-7 via shuffles (no block syncs).
// Stable: ties -> lowest candidate index (lax.top_k semantics).
// ---------------------------------------------------------------------------
__global__ void __launch_bounds__(256) stage1b_kernel() {
    const int lane = threadIdx.x & 31;
    const int q = blockIdx.x*8 + (threadIdx.x >> 5);
    const int rr = q % (NHC*NWC);
    const int qh = (rr / NWC) * 8;
    const int qw = (rr % NWC) * 8;

    float v[6];
    #pragma unroll
    for (int j = 0; j < 6; ++j) v[j] = g_sd[q*SS + j*32 + lane];

    #pragma unroll 1
    for (int k = 0; k < KK; ++k) {
        float bv = v[0]; int bi = lane;
        #pragma unroll
        for (int j = 1; j < 6; ++j) {
            if (v[j] > bv) { bv = v[j]; bi = j*32 + lane; }
        }
        #pragma unroll
        for (int s = 16; s > 0; s >>= 1) {
            float ov = __shfl_xor_sync(0xffffffffu, bv, s);
            int   oi = __shfl_xor_sync(0xffffffffu, bi, s);
            if (ov > bv || (ov == bv && oi < bi)) { bv = ov; bi = oi; }
        }
        if (lane == 0) {
            int base = (q*KK + k)*3;
            g_inds[base + 0] = bi >> 6;                   // ct
            g_inds[base + 1] = qh + ((bi >> 3) & 7) - 4;  // ch (raw)
            g_inds[base + 2] = qw + (bi & 7) - 4;         // cw (raw)
        }
        if ((bi & 31) == lane) {
            int jj = bi >> 5;
            #pragma unroll
            for (int j = 0; j < 6; ++j) if (j == jj) v[j] = -FLT_MAX;
        }
    }
}

// ---------------------------------------------------------------------------
// Stage 2+3 fused v5 (reverted from v6 — prologue-bound, don't split the
// mainloop): float4 channel split; block = 224 threads (7 warps); warp k =
// candidate k. lane: par = lane>>4 (offset parity), c16 = lane&15.
// ---------------------------------------------------------------------------
__global__ void __launch_bounds__(224) stage3_kernel(float* __restrict__ out) {
    const int q  = blockIdx.x;
    const int ft = q / (NHF*NWF);
    const int rr = q % (NHF*NWF);
    const int fi = rr / NWF, fj = rr % NWF;
    const int fh = fi*4, fw = fj*4;

    __shared__ float sp[49*CC];
    __shared__ int   scand[KK*3];
    __shared__ int   soff[KK*49 + 7];   // padded (soff[k][49] read by par=1 tail)

    const int tid = threadIdx.x;
    // query patch, vectorized
    for (int i = tid; i < 49*16; i += 224) {
        int o = i >> 4, c4 = i & 15;
        int y = refl(fh + (o/7) - 3, HH);
        int x = refl(fw + (o%7) - 3, WW);
        reinterpret_cast<float4*>(sp)[i] =
            reinterpret_cast<const float4*>(g_v0t + ((size_t)ft*HWSZ + (size_t)y*WW + x)*CC)[c4];
    }
    if (tid < KK) {
        int it, ih, iw;
        if (tid == 0) { it = ft; ih = fh; iw = fw; }
        else {
            int ci = min(fi >> 1, NHC - 1);
            int cj = min(fj >> 1, NWC - 1);
            int qlin = ft*NHC*NWC + ci*NWC + cj;
            int b = (qlin*KK + tid)*3;
            it = g_inds[b + 0];
            ih = refl(g_inds[b + 1] + (fh - ci*8), HH);
            iw = refl(g_inds[b + 2] + (fw - cj*8), WW);
        }
        scand[tid*3 + 0] = it;
        scand[tid*3 + 1] = ih;
        scand[tid*3 + 2] = iw;
        soff[KK*49 + tid] = 0;   // safe pad
        // inds_f (as float), laid out after dists_f
        size_t ob = (size_t)QF*KK + ((size_t)q*KK + tid)*3;
        out[ob + 0] = (float)it;
        out[ob + 1] = (float)ih;
        out[ob + 2] = (float)iw;
    }
    __syncthreads();

    // cooperative offset table: soff[k*49+o] = (y1*W + x1)*CC (element offset)
    for (int i = tid; i < KK*49; i += 224) {
        int k = i / 49, o = i % 49;
        int y1 = refl(scand[k*3 + 1] + o/7 - 3, HH);
        int x1 = refl(scand[k*3 + 2] + o%7 - 3, WW);
        soff[i] = (y1*WW + x1)*CC;
    }
    __syncthreads();

    const int warp = tid >> 5;
    const int lane = tid & 31;
    const int par  = lane >> 4;       // offset parity
    const int c16  = lane & 15;       // channel quad
    const int it = scand[warp*3 + 0];
    const float* v1b = g_v1t + (size_t)it*HWSZ*CC + 4*c16;
    const int* mysoff = soff + warp*49 + par;
    const float* spl = sp + 4*c16;

    float4 acc = make_float4(0.f, 0.f, 0.f, 0.f);
    #pragma unroll 5
    for (int i = 0; i < 25; ++i) {
        int o = 2*i + par;            // par=1,i=24 -> o=49 reads pad; masked below
        float4 wv = *reinterpret_cast<const float4*>(v1b + mysoff[2*i]);
        float4 pv = *reinterpret_cast<const float4*>(spl + o*CC);
        float m = (o < 49) ? 1.f : 0.f;
        acc.x = fmaf(pv.x*m, wv.x, acc.x);
        acc.y = fmaf(pv.y*m, wv.y, acc.y);
        acc.z = fmaf(pv.z*m, wv.z, acc.z);
        acc.w = fmaf(pv.w*m, wv.w, acc.w);
    }
    float v = (acc.x + acc.y) + (acc.z + acc.w);
    #pragma unroll
    for (int s = 16; s > 0; s >>= 1)
        v += __shfl_down_sync(0xffffffffu, v, s);
    if (lane == 0)
        out[(size_t)q*KK + warp] = v;
}

// ---------------------------------------------------------------------------
extern "C" void kernel_launch(void* const* d_in, const int* in_sizes, int n_in,
                              void* d_out, int out_size) {
    const float* vid0 = (const float*)d_in[0];
    const float* vid1 = (const float*)d_in[1];
    // d_in[2] = flows, unused by the reference

    cudaFuncSetAttribute(stage1a_kernel,
                         cudaFuncAttributeMaxDynamicSharedMemorySize, SV_BYTES);

    // two dummies keep the ncu fixed capture slot on stage1a
    dummy_kernel<<<1, 32>>>();
    dummy_kernel<<<1, 32>>>();

    dim3 tgrid(HWSZ/32, TT, 2);
    transpose_kernel<<<tgrid, 256>>>(vid0, vid1);
    stage1a_kernel<<<dim3(NWC/NQB, NHC, TT), 288, SV_BYTES>>>();
    stage1b_kernel<<<Q1/8, 256>>>();
    stage3_kernel<<<QF, 224>>>((float*)d_out);
}

// round 15
// speedup vs baseline: 1.0791x; 1.0467x over previous
#include <cuda_runtime.h>
#include <float.h>

#define TT   3
#define HH   192
#define WW   192
#define CC   64
#define HWSZ (HH*WW)
#define NHC  24
#define NWC  24
#define Q1   (TT*NHC*NWC)   // 1728
#define NHF  48
#define NWF  48
#define QF   (TT*NHF*NWF)   // 6912
#define KK   7
#define SS   192            // candidates per query

// scratch (static __device__ arrays — allowed; no runtime allocation)
__device__ float g_v0t[TT*HWSZ*CC];
__device__ float g_v1t[TT*HWSZ*CC];
__device__ float g_sd[Q1*SS];
__device__ int   g_inds[Q1*KK*3];

__device__ __forceinline__ int refl(int i, int L) {
    i = i < 0 ? -i : i;
    return (i >= L) ? (2*(L-1) - i) : i;
}

// ---------------------------------------------------------------------------
// Transpose (T,C,H,W) -> (T,H,W,C), channels-last, for both videos.
// ---------------------------------------------------------------------------
__global__ void __launch_bounds__(256) transpose_kernel(const float* __restrict__ v0,
                                                        const float* __restrict__ v1) {
    const float* src = (blockIdx.z == 0) ? v0 : v1;
    float* dst       = (blockIdx.z == 0) ? g_v0t : g_v1t;
    const int t    = blockIdx.y;
    const int pix0 = blockIdx.x * 32;

    __shared__ float tile[CC][33];
    const int tx  = threadIdx.x & 31;
    const int grp = threadIdx.x >> 5;   // 0..7

    #pragma unroll
    for (int cc = 0; cc < CC; cc += 8) {
        int c = cc + grp;
        tile[c][tx] = src[((size_t)(t*CC + c))*HWSZ + pix0 + tx];
    }
    __syncthreads();
    #pragma unroll
    for (int i = 0; i < 8; ++i) {
        int idx = i*256 + threadIdx.x;        // 0..2047
        int pix = idx >> 6;                   // 0..31
        int ch  = idx & 63;
        dst[((size_t)t*HWSZ + pix0 + pix)*CC + ch] = tile[ch][pix];
    }
}

// ---------------------------------------------------------------------------
// Stage 1a (R12-exact, best measured 98.4us): 6-query blocks, quad packing,
// fully-unrolled software-pipelined inner loop.
// grid (4, 24, 3): block = (6 adjacent queries, row qi, t). 288 thr = 9 warps.
// query-slot = tid>>4 (0..17): u = slot%6, qt = slot/6; sub = tid&15;
// dyi = sub>>1, quad = sub&1 -> candidates dxi = 4*quad..4*quad+3.
// Per candidate, per offset (dri,ox): p = sequential fma chain over c=0..63,
// then acc += p in (dri major, ox ascending) order. DO NOT REORDER the
// arithmetic — it reproduces the reference's fp tie resolution bit-for-bit.
// ---------------------------------------------------------------------------
#define NQB     6                     // queries per block
#define WCOLS   (8*NQB + 6)           // 54 col slots
#define CSTR2   68                    // col-slot stride (floats)
#define ROWSTR2 (WCOLS*CSTR2 + 12)    // 3684 floats; mod 32 == 4 (conflict-free)
#define SV_BYTES (14*ROWSTR2*4)       // 206304 bytes dynamic smem

#define LOAD_WA(wb, ab, c4)                                                   \
    do {                                                                      \
        _Pragma("unroll")                                                     \
        for (int j = 0; j < 10; ++j)                                          \
            wb[j] = *reinterpret_cast<const float4*>(vrow + j*CSTR2 + (c4)*4);\
        _Pragma("unroll")                                                     \
        for (int ox = 0; ox < 7; ++ox)                                        \
            ab[ox] = *reinterpret_cast<const float4*>(qrow + xq[ox] + (c4)*4);\
    } while (0)

#define COMPUTE_WA(wb, ab)                                                    \
    do {                                                                      \
        _Pragma("unroll")                                                     \
        for (int d = 0; d < 4; ++d) {                                         \
            _Pragma("unroll")                                                 \
            for (int ox = 0; ox < 7; ++ox) {                                  \
                float4 b = wb[d + ox];                                        \
                p[d][ox] = fmaf(ab[ox].x, b.x, p[d][ox]);                     \
                p[d][ox] = fmaf(ab[ox].y, b.y, p[d][ox]);                     \
                p[d][ox] = fmaf(ab[ox].z, b.z, p[d][ox]);                     \
                p[d][ox] = fmaf(ab[ox].w, b.w, p[d][ox]);                     \
            }                                                                 \
        }                                                                     \
    } while (0)

__global__ void __launch_bounds__(288, 1) stage1a_kernel() {
    extern __shared__ float sv[];

    const int qj0 = blockIdx.x * NQB;
    const int qi  = blockIdx.y;
    const int t   = blockIdx.z;
    const int qh  = qi * 8;
    const int qw0 = qj0 * 8;

    const int tid  = threadIdx.x;
    const int slot = tid >> 4;        // 0..17
    const int u    = slot % NQB;      // query within block
    const int qt   = slot / NQB;      // 0..2
    const int sub  = tid & 15;
    const int dyi  = sub >> 1;        // 0..7
    const int quad = sub & 1;         // 0..1 -> dxi base 4*quad

    // cooperative load: candidate window (once)
    const float* v1base = g_v1t + (size_t)t*HWSZ*CC;
    for (int i = tid; i < 14*WCOLS*16; i += 288) {
        int r   = i / (WCOLS*16);
        int rem = i % (WCOLS*16);
        int s   = rem >> 4;
        int c4  = rem & 15;
        int y = refl(qh - 7 + r, HH);
        int x = refl(qw0 - 7 + s, WW);
        float4 v = reinterpret_cast<const float4*>(v1base + ((size_t)y*WW + x)*CC)[c4];
        *reinterpret_cast<float4*>(sv + r*ROWSTR2 + s*CSTR2 + c4*4) = v;
    }
    __syncthreads();

    const int q  = qt*(NHC*NWC) + qi*NWC + (qj0 + u);
    const int qw = qw0 + u*8;

    // query patch col element-offsets (uniform within slot)
    int xq[7];
    #pragma unroll
    for (int ox = 0; ox < 7; ++ox) xq[ox] = refl(qw + ox - 3, WW) * CC;
    const float* v0base = g_v0t + (size_t)qt*HWSZ*CC;

    float acc[4] = {0.f, 0.f, 0.f, 0.f};
    const float* svw = sv + (8*u + 4*quad)*CSTR2;

    for (int dri = 0; dri < 7; ++dri) {
        const int yq = refl(qh + dri - 3, HH);
        const float* qrow = v0base + (size_t)yq*WW*CC;
        const float* vrow = svw + (dyi + dri)*ROWSTR2;

        float p[4][7];
        #pragma unroll
        for (int d = 0; d < 4; ++d)
            #pragma unroll
            for (int ox = 0; ox < 7; ++ox) p[d][ox] = 0.f;

        // software pipeline: prefetch one c4-iter ahead into alternating bufs
        float4 w0[10], a0[7], w1[10], a1[7];
        LOAD_WA(w0, a0, 0);
        #pragma unroll
        for (int c4 = 0; c4 < 16; c4 += 2) {
            LOAD_WA(w1, a1, c4 + 1);     // prefetch c4+1
            COMPUTE_WA(w0, a0);          // compute c4
            if (c4 + 2 < 16)
                LOAD_WA(w0, a0, c4 + 2); // prefetch c4+2
            COMPUTE_WA(w1, a1);          // compute c4+1
        }
        #pragma unroll
        for (int d = 0; d < 4; ++d)
            #pragma unroll
            for (int ox = 0; ox < 7; ++ox) acc[d] += p[d][ox];
    }

    float4 res = make_float4(acc[0], acc[1], acc[2], acc[3]);
    *reinterpret_cast<float4*>(&g_sd[q*SS + t*64 + dyi*8 + 4*quad]) = res;
}

// ---------------------------------------------------------------------------
// Stage 1b: warp-per-query top-7 via shuffles (no block syncs).
// Stable: ties -> lowest candidate index (lax.top_k semantics).
// ---------------------------------------------------------------------------
__global__ void __launch_bounds__(256) stage1b_kernel() {
    const int lane = threadIdx.x & 31;
    const int q = blockIdx.x*8 + (threadIdx.x >> 5);
    const int rr = q % (NHC*NWC);
    const int qh = (rr / NWC) * 8;
    const int qw = (rr % NWC) * 8;

    float v[6];
    #pragma unroll
    for (int j = 0; j < 6; ++j) v[j] = g_sd[q*SS + j*32 + lane];

    #pragma unroll 1
    for (int k = 0; k < KK; ++k) {
        float bv = v[0]; int bi = lane;
        #pragma unroll
        for (int j = 1; j < 6; ++j) {
            if (v[j] > bv) { bv = v[j]; bi = j*32 + lane; }
        }
        #pragma unroll
        for (int s = 16; s > 0; s >>= 1) {
            float ov = __shfl_xor_sync(0xffffffffu, bv, s);
            int   oi = __shfl_xor_sync(0xffffffffu, bi, s);
            if (ov > bv || (ov == bv && oi < bi)) { bv = ov; bi = oi; }
        }
        if (lane == 0) {
            int base = (q*KK + k)*3;
            g_inds[base + 0] = bi >> 6;                   // ct
            g_inds[base + 1] = qh + ((bi >> 3) & 7) - 4;  // ch (raw)
            g_inds[base + 2] = qw + (bi & 7) - 4;         // cw (raw)
        }
        if ((bi & 31) == lane) {
            int jj = bi >> 5;
            #pragma unroll
            for (int j = 0; j < 6; ++j) if (j == jj) v[j] = -FLT_MAX;
        }
    }
}

// ---------------------------------------------------------------------------
// Stage 2+3 fused v5.1: float4 channel split; tail mask replaced by a
// ZERO PIXEL appended to the smem patch (o=49 pad reads zeros -> contributes
// nothing, no per-iter mask multiplies).
// block = 224 threads (7 warps); warp k = candidate k.
// lane: par = lane>>4 (offset parity), c16 = lane&15 (channel quad).
// ---------------------------------------------------------------------------
__global__ void __launch_bounds__(224) stage3_kernel(float* __restrict__ out) {
    const int q  = blockIdx.x;
    const int ft = q / (NHF*NWF);
    const int rr = q % (NHF*NWF);
    const int fi = rr / NWF, fj = rr % NWF;
    const int fh = fi*4, fw = fj*4;

    __shared__ float sp[50*CC];         // 49 patch pixels + 1 zero pixel
    __shared__ int   scand[KK*3];
    __shared__ int   soff[KK*49 + 7];   // padded (soff[k][49] read by par=1 tail)

    const int tid = threadIdx.x;
    // query patch, vectorized
    for (int i = tid; i < 49*16; i += 224) {
        int o = i >> 4, c4 = i & 15;
        int y = refl(fh + (o/7) - 3, HH);
        int x = refl(fw + (o%7) - 3, WW);
        reinterpret_cast<float4*>(sp)[i] =
            reinterpret_cast<const float4*>(g_v0t + ((size_t)ft*HWSZ + (size_t)y*WW + x)*CC)[c4];
    }
    // zero pixel at o=49
    if (tid < 16)
        reinterpret_cast<float4*>(sp)[49*16 + tid] = make_float4(0.f, 0.f, 0.f, 0.f);
    if (tid < KK) {
        int it, ih, iw;
        if (tid == 0) { it = ft; ih = fh; iw = fw; }
        else {
            int ci = min(fi >> 1, NHC - 1);
            int cj = min(fj >> 1, NWC - 1);
            int qlin = ft*NHC*NWC + ci*NWC + cj;
            int b = (qlin*KK + tid)*3;
            it = g_inds[b + 0];
            ih = refl(g_inds[b + 1] + (fh - ci*8), HH);
            iw = refl(g_inds[b + 2] + (fw - cj*8), WW);
        }
        scand[tid*3 + 0] = it;
        scand[tid*3 + 1] = ih;
        scand[tid*3 + 2] = iw;
        soff[KK*49 + tid] = 0;   // safe pad (valid global offset; pv=0 kills it)
        // inds_f (as float), laid out after dists_f
        size_t ob = (size_t)QF*KK + ((size_t)q*KK + tid)*3;
        out[ob + 0] = (float)it;
        out[ob + 1] = (float)ih;
        out[ob + 2] = (float)iw;
    }
    __syncthreads();

    // cooperative offset table: soff[k*49+o] = (y1*W + x1)*CC (element offset)
    for (int i = tid; i < KK*49; i += 224) {
        int k = i / 49, o = i % 49;
        int y1 = refl(scand[k*3 + 1] + o/7 - 3, HH);
        int x1 = refl(scand[k*3 + 2] + o%7 - 3, WW);
        soff[i] = (y1*WW + x1)*CC;
    }
    __syncthreads();

    const int warp = tid >> 5;
    const int lane = tid & 31;
    const int par  = lane >> 4;       // offset parity
    const int c16  = lane & 15;       // channel quad
    const int it = scand[warp*3 + 0];
    const float* v1b = g_v1t + (size_t)it*HWSZ*CC + 4*c16;
    const int* mysoff = soff + warp*49 + par;
    const float* spl = sp + 4*c16;

    float4 acc = make_float4(0.f, 0.f, 0.f, 0.f);
    #pragma unroll 5
    for (int i = 0; i < 25; ++i) {
        int o = 2*i + par;            // par=1,i=24 -> o=49 hits the zero pixel
        float4 wv = *reinterpret_cast<const float4*>(v1b + mysoff[2*i]);
        float4 pv = *reinterpret_cast<const float4*>(spl + o*CC);
        acc.x = fmaf(pv.x, wv.x, acc.x);
        acc.y = fmaf(pv.y, wv.y, acc.y);
        acc.z = fmaf(pv.z, wv.z, acc.z);
        acc.w = fmaf(pv.w, wv.w, acc.w);
    }
    float v = (acc.x + acc.y) + (acc.z + acc.w);
    #pragma unroll
    for (int s = 16; s > 0; s >>= 1)
        v += __shfl_down_sync(0xffffffffu, v, s);
    if (lane == 0)
        out[(size_t)q*KK + warp] = v;
}

// ---------------------------------------------------------------------------
extern "C" void kernel_launch(void* const* d_in, const int* in_sizes, int n_in,
                              void* d_out, int out_size) {
    const float* vid0 = (const float*)d_in[0];
    const float* vid1 = (const float*)d_in[1];
    // d_in[2] = flows, unused by the reference

    cudaFuncSetAttribute(stage1a_kernel,
                         cudaFuncAttributeMaxDynamicSharedMemorySize, SV_BYTES);

    dim3 tgrid(HWSZ/32, TT, 2);
    transpose_kernel<<<tgrid, 256>>>(vid0, vid1);
    stage1a_kernel<<<dim3(NWC/NQB, NHC, TT), 288, SV_BYTES>>>();
    stage1b_kernel<<<Q1/8, 256>>>();
    stage3_kernel<<<QF, 224>>>((float*)d_out);
}